// round 1
// baseline (speedup 1.0000x reference)
#include <cuda_runtime.h>
#include <math.h>

// ---------------------------------------------------------------------------
// Output layout (tuple flattened in order):
// offsets [4,256,256,2], sizes [4,256,256,2], weights [4,256,256,1],
// pred_cls [4,3], seg_sel [256,32,32,1], score_sel [256,1]
// ---------------------------------------------------------------------------
#define OFF_OFFSETS 0
#define OFF_SIZES   524288
#define OFF_WEIGHTS 1048576
#define OFF_PREDCLS 1310720
#define OFF_SEG     1310732
#define OFF_SCORE   1572876

// Scratch (device globals; no allocation allowed)
__device__ float g_x1[4u * 256u * 256u * 256u];      // conv1 out   256MB
__device__ float g_x2[4u * 256u * 256u * 256u];      // conv2 out   256MB
__device__ float g_crops[256u * 32u * 32u * 64u];    // crops        64MB
__device__ float g_s1[256u * 32u * 32u * 96u];       // sc1 out      96MB
__device__ float g_s2[256u * 32u * 32u * 96u];       // sc2 out      96MB
__device__ int   g_cls[4];

// ---------------------------------------------------------------------------
// Classification head: mean -> fc1 -> fc2 -> fc3 -> softmax/argmax
// ---------------------------------------------------------------------------
__global__ void cls_kernel(const float* __restrict__ feat5,
                           const float* __restrict__ fc1_w, const float* __restrict__ fc1_b,
                           const float* __restrict__ fc2_w, const float* __restrict__ fc2_b,
                           const float* __restrict__ fc3_w, const float* __restrict__ fc3_b,
                           float* __restrict__ out_predcls, int* __restrict__ cls) {
    int b = blockIdx.x;
    int t = threadIdx.x;  // 256
    __shared__ float g0[256], g1[256], lg[3];
    const float* f = feat5 + (size_t)b * 16 * 16 * 256;
    float s = 0.f;
    #pragma unroll 4
    for (int p = 0; p < 256; p++) s += f[p * 256 + t];
    g0[t] = s * (1.0f / 256.0f);
    __syncthreads();
    float a = fc1_b[t];
    #pragma unroll 4
    for (int k = 0; k < 256; k++) a = fmaf(g0[k], fc1_w[k * 256 + t], a);
    g1[t] = fmaxf(a, 0.f);
    __syncthreads();
    a = fc2_b[t];
    #pragma unroll 4
    for (int k = 0; k < 256; k++) a = fmaf(g1[k], fc2_w[k * 256 + t], a);
    g0[t] = fmaxf(a, 0.f);
    __syncthreads();
    if (t < 3) {
        a = fc3_b[t];
        for (int k = 0; k < 256; k++) a = fmaf(g0[k], fc3_w[k * 3 + t], a);
        lg[t] = a;
    }
    __syncthreads();
    if (t == 0) {
        float m = fmaxf(lg[0], fmaxf(lg[1], lg[2]));
        float e0 = expf(lg[0] - m), e1 = expf(lg[1] - m), e2 = expf(lg[2] - m);
        float inv = 1.f / (e0 + e1 + e2);
        out_predcls[b * 3 + 0] = e0 * inv;
        out_predcls[b * 3 + 1] = e1 * inv;
        out_predcls[b * 3 + 2] = e2 * inv;
        int c = 0;
        if (lg[1] > lg[0]) c = 1;
        if (lg[2] > lg[c]) c = 2;
        cls[b] = c;
    }
}

// ---------------------------------------------------------------------------
// Generic 3x3 SAME conv (NHWC), implicit GEMM.
// Block: 256 threads. Tile: 128 pixels (16y x 8x) x 128 out channels.
// Each thread: 8 pixels x 8 channels register block.
// grid: (W/8, H/16, nimg * ntiles)
// ---------------------------------------------------------------------------
template <int CIN, int COUT, bool RELU>
__global__ __launch_bounds__(256, 2)
void conv3x3(const float* __restrict__ in, const float* __restrict__ w,
             const float* __restrict__ bias, float* __restrict__ out,
             int H, int W) {
    constexpr int NT = (COUT + 127) / 128;
    int ntile = (int)(blockIdx.z % NT);
    int img   = (int)(blockIdx.z / NT);
    int x0 = blockIdx.x * 8, y0 = blockIdx.y * 16;
    int cobase = ntile * 128;

    __shared__ __align__(16) float As[8][132];
    __shared__ __align__(16) float Bs[8][128];

    int t = threadIdx.x;
    // A load indices
    int lp = t >> 1;            // pixel 0..127
    int lhalf = t & 1;          // 0/1 (which 4 channels)
    int lpy = lp >> 3, lpx = lp & 7;
    // B load indices
    int bk = t >> 5;            // k row 0..7
    int bco = (t & 31) * 4;     // cout 0..124
    // compute indices
    int row = t >> 4;           // pixel row 0..15
    int col = t & 15;           // cout group 0..15

    float acc[8][8];
    #pragma unroll
    for (int i = 0; i < 8; i++)
        #pragma unroll
        for (int j = 0; j < 8; j++) acc[i][j] = 0.f;

    const int KCHUNKS = CIN * 9 / 8;
    const float* inimg = in + (size_t)img * H * W * CIN;

    for (int kc = 0; kc < KCHUNKS; kc++) {
        int kbase = kc * 8;
        int tap = kbase / CIN;
        int ciA = (kbase % CIN) + lhalf * 4;
        int dy = tap / 3 - 1, dx = tap % 3 - 1;
        int gy = y0 + lpy + dy, gx = x0 + lpx + dx;
        float4 va = make_float4(0.f, 0.f, 0.f, 0.f);
        if (gy >= 0 && gy < H && gx >= 0 && gx < W)
            va = *(const float4*)(inimg + ((size_t)gy * W + gx) * CIN + ciA);
        float4 vb = make_float4(0.f, 0.f, 0.f, 0.f);
        {
            int kg = kbase + bk;
            int cog = cobase + bco;
            if (cog < COUT) {
                const float* wp = w + (size_t)kg * COUT + cog;
                if (cog + 3 < COUT) vb = *(const float4*)wp;
                else {
                    vb.x = wp[0];
                    if (cog + 1 < COUT) vb.y = wp[1];
                    if (cog + 2 < COUT) vb.z = wp[2];
                }
            }
        }
        __syncthreads();
        As[lhalf * 4 + 0][lp] = va.x;
        As[lhalf * 4 + 1][lp] = va.y;
        As[lhalf * 4 + 2][lp] = va.z;
        As[lhalf * 4 + 3][lp] = va.w;
        *(float4*)&Bs[bk][bco] = vb;
        __syncthreads();
        #pragma unroll
        for (int k = 0; k < 8; k++) {
            float a[8], b[8];
            *(float4*)&a[0] = *(const float4*)&As[k][row * 8];
            *(float4*)&a[4] = *(const float4*)&As[k][row * 8 + 4];
            *(float4*)&b[0] = *(const float4*)&Bs[k][col * 8];
            *(float4*)&b[4] = *(const float4*)&Bs[k][col * 8 + 4];
            #pragma unroll
            for (int i = 0; i < 8; i++)
                #pragma unroll
                for (int j = 0; j < 8; j++)
                    acc[i][j] = fmaf(a[i], b[j], acc[i][j]);
        }
    }

    // epilogue
    int gy = y0 + row;
    float bv[8];
    #pragma unroll
    for (int j = 0; j < 8; j++) {
        int cog = cobase + col * 8 + j;
        bv[j] = (cog < COUT) ? bias[cog] : 0.f;
    }
    float* outimg = out + (size_t)img * H * W * COUT;
    #pragma unroll
    for (int i = 0; i < 8; i++) {
        int gx = x0 + i;
        float v[8];
        #pragma unroll
        for (int j = 0; j < 8; j++) {
            float r = acc[i][j] + bv[j];
            if (RELU) r = fmaxf(r, 0.f);
            v[j] = r;
        }
        int cog = cobase + col * 8;
        float* op = outimg + ((size_t)gy * W + gx) * COUT + cog;
        if (cog + 7 < COUT) {
            *(float4*)op = *(float4*)&v[0];
            *(float4*)(op + 4) = *(float4*)&v[4];
        } else {
            #pragma unroll
            for (int j = 0; j < 8; j++)
                if (cog + j < COUT) op[j] = v[j];
        }
    }
}

// ---------------------------------------------------------------------------
// Fused reg/wt conv with per-batch class selection: 5 output channels only.
// grid (16,16,4), block 256 (16x16 pixel tile)
// ---------------------------------------------------------------------------
__global__ void regsel_kernel(const float* __restrict__ x,
                              const float* __restrict__ reg_w, const float* __restrict__ reg_b,
                              const float* __restrict__ wt_w,  const float* __restrict__ wt_b,
                              const int* __restrict__ cls, float* __restrict__ out) {
    int b = blockIdx.z;
    int c = cls[b];
    __shared__ __align__(16) float ws[9 * 256 * 5];   // 46080 B
    int t = threadIdx.x;
    for (int i = t; i < 9 * 256; i += 256) {
        const float* rp = reg_w + (size_t)i * 12 + 4 * c;
        float* wp = ws + i * 5;
        wp[0] = rp[0]; wp[1] = rp[1]; wp[2] = rp[2]; wp[3] = rp[3];
        wp[4] = wt_w[(size_t)i * 3 + c];
    }
    __syncthreads();
    int px = blockIdx.x * 16 + (t & 15);
    int py = blockIdx.y * 16 + (t >> 4);
    float a0 = reg_b[4 * c], a1 = reg_b[4 * c + 1], a2 = reg_b[4 * c + 2],
          a3 = reg_b[4 * c + 3], a4 = wt_b[c];
    const float* xi = x + (size_t)b * 256 * 256 * 256;
    for (int tap = 0; tap < 9; tap++) {
        int yy = py + tap / 3 - 1, xx = px + tap % 3 - 1;
        if (yy < 0 || yy >= 256 || xx < 0 || xx >= 256) continue;
        const float* ip = xi + ((size_t)yy * 256 + xx) * 256;
        const float* wp = ws + tap * 256 * 5;
        #pragma unroll 2
        for (int ci = 0; ci < 256; ci += 4) {
            float4 v = *(const float4*)(ip + ci);
            float wl[20];
            const float4* w4 = (const float4*)(wp + ci * 5);
            #pragma unroll
            for (int q = 0; q < 5; q++) ((float4*)wl)[q] = w4[q];
            a0 = fmaf(v.x, wl[0], a0);  a1 = fmaf(v.x, wl[1], a1);
            a2 = fmaf(v.x, wl[2], a2);  a3 = fmaf(v.x, wl[3], a3);  a4 = fmaf(v.x, wl[4], a4);
            a0 = fmaf(v.y, wl[5], a0);  a1 = fmaf(v.y, wl[6], a1);
            a2 = fmaf(v.y, wl[7], a2);  a3 = fmaf(v.y, wl[8], a3);  a4 = fmaf(v.y, wl[9], a4);
            a0 = fmaf(v.z, wl[10], a0); a1 = fmaf(v.z, wl[11], a1);
            a2 = fmaf(v.z, wl[12], a2); a3 = fmaf(v.z, wl[13], a3); a4 = fmaf(v.z, wl[14], a4);
            a0 = fmaf(v.w, wl[15], a0); a1 = fmaf(v.w, wl[16], a1);
            a2 = fmaf(v.w, wl[17], a2); a3 = fmaf(v.w, wl[18], a3); a4 = fmaf(v.w, wl[19], a4);
        }
    }
    size_t pix = ((size_t)b * 256 + py) * 256 + px;
    out[OFF_OFFSETS + pix * 2 + 0] = a0;
    out[OFF_OFFSETS + pix * 2 + 1] = a1;
    out[OFF_SIZES   + pix * 2 + 0] = a2;
    out[OFF_SIZES   + pix * 2 + 1] = a3;
    out[OFF_WEIGHTS + pix] = a4;
}

// ---------------------------------------------------------------------------
// Bilinear crop (TF crop_and_resize), 32x32, one block per box.
// ---------------------------------------------------------------------------
__global__ void crop_kernel(const float* __restrict__ feat0,
                            const float* __restrict__ boxes,
                            float* __restrict__ crops) {
    int n = blockIdx.x;            // 0..255 (b*64+p)
    int b = n >> 6;
    const int H = 512, W = 512, C = 64;
    __shared__ int sy0[32], sx0[32];
    __shared__ float swy[32], swx[32];
    const float* bx = boxes + (size_t)n * 4;
    float y1 = bx[0], x1 = bx[1], y2 = bx[2], x2 = bx[3];
    int t = threadIdx.x;
    if (t < 32) {
        float tt = (float)t / 31.0f;
        float ys = y1 * (H - 1) + tt * (y2 - y1) * (H - 1);
        int yy0 = (int)floorf(ys);
        yy0 = min(max(yy0, 0), H - 2);
        sy0[t] = yy0; swy[t] = ys - (float)yy0;
    } else if (t < 64) {
        int i = t - 32;
        float tt = (float)i / 31.0f;
        float xs = x1 * (W - 1) + tt * (x2 - x1) * (W - 1);
        int xx0 = (int)floorf(xs);
        xx0 = min(max(xx0, 0), W - 2);
        sx0[i] = xx0; swx[i] = xs - (float)xx0;
    }
    __syncthreads();
    const float* f = feat0 + (size_t)b * H * W * C;
    float* o = crops + (size_t)n * 32 * 32 * C;
    for (int idx = t; idx < 32 * 32 * C; idx += blockDim.x) {
        int c  = idx & 63;
        int ix = (idx >> 6) & 31;
        int iy = idx >> 11;
        int yy0 = sy0[iy], xx0 = sx0[ix];
        float wy = swy[iy], wx = swx[ix];
        const float* p00 = f + ((size_t)yy0 * W + xx0) * C + c;
        float v00 = p00[0], v01 = p00[C], v10 = p00[(size_t)W * C], v11 = p00[(size_t)W * C + C];
        float top = v00 * (1.f - wx) + v01 * wx;
        float bot = v10 * (1.f - wx) + v11 * wx;
        o[idx] = top * (1.f - wy) + bot * wy;
    }
}

// ---------------------------------------------------------------------------
// so conv with class selection: 1 output channel per crop.
// ---------------------------------------------------------------------------
__global__ void sosel_kernel(const float* __restrict__ s2,
                             const float* __restrict__ so_w, const float* __restrict__ so_b,
                             const int* __restrict__ cls, float* __restrict__ out) {
    int n = blockIdx.x;
    int c = cls[n >> 6];
    __shared__ __align__(16) float ws[9 * 96];
    int t = threadIdx.x;
    for (int i = t; i < 864; i += 256) ws[i] = so_w[(size_t)i * 3 + c];
    __syncthreads();
    float bias = so_b[c];
    const float* sp = s2 + (size_t)n * 32 * 32 * 96;
    for (int pix = t; pix < 1024; pix += 256) {
        int py = pix >> 5, px = pix & 31;
        float acc = bias;
        for (int tap = 0; tap < 9; tap++) {
            int yy = py + tap / 3 - 1, xx = px + tap % 3 - 1;
            if (yy < 0 || yy >= 32 || xx < 0 || xx >= 32) continue;
            const float* ip = sp + ((size_t)yy * 32 + xx) * 96;
            const float* wp = ws + tap * 96;
            #pragma unroll 4
            for (int ci = 0; ci < 96; ci += 4) {
                float4 v = *(const float4*)(ip + ci);
                float4 w = *(const float4*)(wp + ci);
                acc = fmaf(v.x, w.x, acc);
                acc = fmaf(v.y, w.y, acc);
                acc = fmaf(v.z, w.z, acc);
                acc = fmaf(v.w, w.w, acc);
            }
        }
        out[OFF_SEG + (size_t)n * 1024 + pix] = acc;
    }
}

// ---------------------------------------------------------------------------
// Score head: 4x4 avg pool -> dense 6144->256 -> 256->256 -> 256->3 (select)
// One block per crop.
// ---------------------------------------------------------------------------
__global__ void score_kernel(const float* __restrict__ s2,
                             const float* __restrict__ sd1_w, const float* __restrict__ sd1_b,
                             const float* __restrict__ sd2_w, const float* __restrict__ sd2_b,
                             const float* __restrict__ sd3_w, const float* __restrict__ sd3_b,
                             const int* __restrict__ cls, float* __restrict__ out) {
    int n = blockIdx.x;
    int t = threadIdx.x;  // 256
    __shared__ float pooled[6144];
    __shared__ float h1[256], h2[256];
    const float* sp = s2 + (size_t)n * 32 * 32 * 96;
    for (int o = t; o < 6144; o += 256) {
        int c  = o % 96;
        int px = (o / 96) & 7;
        int py = o / 768;
        float s = 0.f;
        #pragma unroll
        for (int i = 0; i < 4; i++)
            #pragma unroll
            for (int j = 0; j < 4; j++)
                s += sp[(((size_t)(py * 4 + i)) * 32 + (px * 4 + j)) * 96 + c];
        pooled[o] = s * (1.f / 16.f);
    }
    __syncthreads();
    float a = sd1_b[t];
    #pragma unroll 4
    for (int k = 0; k < 6144; k++) a = fmaf(pooled[k], sd1_w[(size_t)k * 256 + t], a);
    h1[t] = fmaxf(a, 0.f);
    __syncthreads();
    a = sd2_b[t];
    #pragma unroll 4
    for (int k = 0; k < 256; k++) a = fmaf(h1[k], sd2_w[k * 256 + t], a);
    h2[t] = fmaxf(a, 0.f);
    __syncthreads();
    if (t == 0) {
        int c = cls[n >> 6];
        float acc = sd3_b[c];
        for (int k = 0; k < 256; k++) acc = fmaf(h2[k], sd3_w[k * 3 + c], acc);
        out[OFF_SCORE + n] = acc;
    }
}

// ---------------------------------------------------------------------------
extern "C" void kernel_launch(void* const* d_in, const int* in_sizes, int n_in,
                              void* d_out, int out_size) {
    (void)in_sizes; (void)n_in; (void)out_size;
    const float* feat0 = (const float*)d_in[0];
    const float* feat1 = (const float*)d_in[1];
    const float* feat5 = (const float*)d_in[2];
    const float* boxes = (const float*)d_in[3];
    const float* cb1_w = (const float*)d_in[4];
    const float* cb1_b = (const float*)d_in[5];
    const float* cb2_w = (const float*)d_in[6];
    const float* cb2_b = (const float*)d_in[7];
    const float* reg_w = (const float*)d_in[8];
    const float* reg_b = (const float*)d_in[9];
    const float* wt_w  = (const float*)d_in[10];
    const float* wt_b  = (const float*)d_in[11];
    const float* fc1_w = (const float*)d_in[12];
    const float* fc1_b = (const float*)d_in[13];
    const float* fc2_w = (const float*)d_in[14];
    const float* fc2_b = (const float*)d_in[15];
    const float* fc3_w = (const float*)d_in[16];
    const float* fc3_b = (const float*)d_in[17];
    const float* sc1_w = (const float*)d_in[18];
    const float* sc1_b = (const float*)d_in[19];
    const float* sc2_w = (const float*)d_in[20];
    const float* sc2_b = (const float*)d_in[21];
    const float* so_w  = (const float*)d_in[22];
    const float* so_b  = (const float*)d_in[23];
    const float* sd1_w = (const float*)d_in[24];
    const float* sd1_b = (const float*)d_in[25];
    const float* sd2_w = (const float*)d_in[26];
    const float* sd2_b = (const float*)d_in[27];
    const float* sd3_w = (const float*)d_in[28];
    const float* sd3_b = (const float*)d_in[29];
    float* out = (float*)d_out;

    void *px1, *px2, *pcrops, *ps1, *ps2, *pcls;
    cudaGetSymbolAddress(&px1, g_x1);
    cudaGetSymbolAddress(&px2, g_x2);
    cudaGetSymbolAddress(&pcrops, g_crops);
    cudaGetSymbolAddress(&ps1, g_s1);
    cudaGetSymbolAddress(&ps2, g_s2);
    cudaGetSymbolAddress(&pcls, g_cls);
    float* x1 = (float*)px1;
    float* x2 = (float*)px2;
    float* crops = (float*)pcrops;
    float* s1 = (float*)ps1;
    float* s2 = (float*)ps2;
    int* cls = (int*)pcls;

    // classification first (reg/seg selection depends on cls)
    cls_kernel<<<4, 256>>>(feat5, fc1_w, fc1_b, fc2_w, fc2_b, fc3_w, fc3_b,
                           out + OFF_PREDCLS, cls);

    // crop + segmentation branch
    crop_kernel<<<256, 256>>>(feat0, boxes, crops);
    conv3x3<64, 96, true><<<dim3(4, 2, 256), 256>>>(crops, sc1_w, sc1_b, s1, 32, 32);
    conv3x3<96, 96, true><<<dim3(4, 2, 256), 256>>>(s1, sc2_w, sc2_b, s2, 32, 32);
    sosel_kernel<<<256, 256>>>(s2, so_w, so_b, cls, out);
    score_kernel<<<256, 256>>>(s2, sd1_w, sd1_b, sd2_w, sd2_b, sd3_w, sd3_b, cls, out);

    // regression branch
    conv3x3<128, 256, true><<<dim3(32, 16, 4 * 2), 256>>>(feat1, cb1_w, cb1_b, x1, 256, 256);
    conv3x3<256, 256, true><<<dim3(32, 16, 4 * 2), 256>>>(x1, cb2_w, cb2_b, x2, 256, 256);
    regsel_kernel<<<dim3(16, 16, 4), 256>>>(x2, reg_w, reg_b, wt_w, wt_b, cls, out);
}

// round 2
// speedup vs baseline: 1.1212x; 1.1212x over previous
#include <cuda_runtime.h>
#include <math.h>

typedef unsigned long long u64;

// ---------------------------------------------------------------------------
// Output layout (tuple flattened in order):
// offsets [4,256,256,2], sizes [4,256,256,2], weights [4,256,256,1],
// pred_cls [4,3], seg_sel [256,32,32,1], score_sel [256,1]
// ---------------------------------------------------------------------------
#define OFF_OFFSETS 0
#define OFF_SIZES   524288
#define OFF_WEIGHTS 1048576
#define OFF_PREDCLS 1310720
#define OFF_SEG     1310732
#define OFF_SCORE   1572876

// Scratch (device globals; no allocation allowed)
__device__ float g_x1[4u * 256u * 256u * 256u];      // conv1 out   256MB
__device__ float g_x2[4u * 256u * 256u * 256u];      // conv2 out   256MB
__device__ float g_crops[256u * 32u * 32u * 64u];    // crops        64MB
__device__ float g_s1[256u * 32u * 32u * 96u];       // sc1 out      96MB
__device__ float g_s2[256u * 32u * 32u * 96u];       // sc2 out      96MB
__device__ int   g_cls[4];

// packed f32x2 helpers (FFMA2 — only reachable via PTX)
__device__ __forceinline__ u64 dup_f32(float x) {
    u64 r;
    asm("mov.b64 %0, {%1, %1};" : "=l"(r) : "f"(x));
    return r;
}
__device__ __forceinline__ void ffma2(u64& acc, u64 a, u64 b) {
    asm("fma.rn.f32x2 %0, %1, %2, %0;" : "+l"(acc) : "l"(a), "l"(b));
}

// ---------------------------------------------------------------------------
// Classification head: mean -> fc1 -> fc2 -> fc3 -> softmax/argmax
// ---------------------------------------------------------------------------
__global__ void cls_kernel(const float* __restrict__ feat5,
                           const float* __restrict__ fc1_w, const float* __restrict__ fc1_b,
                           const float* __restrict__ fc2_w, const float* __restrict__ fc2_b,
                           const float* __restrict__ fc3_w, const float* __restrict__ fc3_b,
                           float* __restrict__ out_predcls, int* __restrict__ cls) {
    int b = blockIdx.x;
    int t = threadIdx.x;  // 256
    __shared__ float g0[256], g1[256], lg[3];
    const float* f = feat5 + (size_t)b * 16 * 16 * 256;
    float s = 0.f;
    #pragma unroll 4
    for (int p = 0; p < 256; p++) s += f[p * 256 + t];
    g0[t] = s * (1.0f / 256.0f);
    __syncthreads();
    float a = fc1_b[t];
    #pragma unroll 4
    for (int k = 0; k < 256; k++) a = fmaf(g0[k], fc1_w[k * 256 + t], a);
    g1[t] = fmaxf(a, 0.f);
    __syncthreads();
    a = fc2_b[t];
    #pragma unroll 4
    for (int k = 0; k < 256; k++) a = fmaf(g1[k], fc2_w[k * 256 + t], a);
    g0[t] = fmaxf(a, 0.f);
    __syncthreads();
    if (t < 3) {
        a = fc3_b[t];
        for (int k = 0; k < 256; k++) a = fmaf(g0[k], fc3_w[k * 3 + t], a);
        lg[t] = a;
    }
    __syncthreads();
    if (t == 0) {
        float m = fmaxf(lg[0], fmaxf(lg[1], lg[2]));
        float e0 = expf(lg[0] - m), e1 = expf(lg[1] - m), e2 = expf(lg[2] - m);
        float inv = 1.f / (e0 + e1 + e2);
        out_predcls[b * 3 + 0] = e0 * inv;
        out_predcls[b * 3 + 1] = e1 * inv;
        out_predcls[b * 3 + 2] = e2 * inv;
        int c = 0;
        if (lg[1] > lg[0]) c = 1;
        if (lg[2] > lg[c]) c = 2;
        cls[b] = c;
    }
}

// ---------------------------------------------------------------------------
// Generic 3x3 SAME conv (NHWC), implicit GEMM, FFMA2 mainloop, double-buffered.
// Block: 256 threads. Tile: 128 pixels (16y x 8x) x 128 out channels.
// Each thread: 8 pixels x 8 channels (4 packed f32x2 pairs) register block.
// grid: (W/8, H/16, nimg * ntiles)
// ---------------------------------------------------------------------------
template <int CIN, int COUT, bool RELU>
__global__ __launch_bounds__(256, 2)
void conv3x3(const float* __restrict__ in, const float* __restrict__ w,
             const float* __restrict__ bias, float* __restrict__ out,
             int H, int W) {
    constexpr int NT = (COUT + 127) / 128;
    int ntile = (int)(blockIdx.z % NT);
    int img   = (int)(blockIdx.z / NT);
    int x0 = blockIdx.x * 8, y0 = blockIdx.y * 16;
    int cobase = ntile * 128;

    __shared__ __align__(16) float As[2][8][132];
    __shared__ __align__(16) float Bs[2][8][128];

    int t = threadIdx.x;
    // A load indices
    int lp = t >> 1;            // pixel 0..127
    int lhalf = t & 1;          // 0/1 (which 4 channels)
    int lpy = lp >> 3, lpx = lp & 7;
    // B load indices
    int bk = t >> 5;            // k row 0..7
    int bco = (t & 31) * 4;     // cout 0..124
    // compute indices
    int row = t >> 4;           // pixel row 0..15
    int col = t & 15;           // cout group 0..15

    u64 acc2[8][4];
    #pragma unroll
    for (int i = 0; i < 8; i++)
        #pragma unroll
        for (int j = 0; j < 4; j++) acc2[i][j] = 0ull;

    const int KCHUNKS = CIN * 9 / 8;
    const float* inimg = in + (size_t)img * H * W * CIN;

    // --- prefetch chunk 0 into regs ---
    float4 va, vb;
    {
        int kbase = 0;
        int ciA = lhalf * 4;
        int gy = y0 + lpy - 1, gx = x0 + lpx - 1;   // tap 0 = (-1,-1)
        va = make_float4(0.f, 0.f, 0.f, 0.f);
        if (gy >= 0 && gy < H && gx >= 0 && gx < W)
            va = *(const float4*)(inimg + ((size_t)gy * W + gx) * CIN + ciA);
        vb = make_float4(0.f, 0.f, 0.f, 0.f);
        int kg = kbase + bk;
        int cog = cobase + bco;
        if (cog < COUT) {
            const float* wp = w + (size_t)kg * COUT + cog;
            if (cog + 3 < COUT) vb = *(const float4*)wp;
            else {
                vb.x = wp[0];
                if (cog + 1 < COUT) vb.y = wp[1];
                if (cog + 2 < COUT) vb.z = wp[2];
            }
        }
    }

    for (int kc = 0; kc < KCHUNKS; kc++) {
        int buf = kc & 1;
        // store prefetched chunk
        As[buf][lhalf * 4 + 0][lp] = va.x;
        As[buf][lhalf * 4 + 1][lp] = va.y;
        As[buf][lhalf * 4 + 2][lp] = va.z;
        As[buf][lhalf * 4 + 3][lp] = va.w;
        *(float4*)&Bs[buf][bk][bco] = vb;

        // prefetch next chunk
        if (kc + 1 < KCHUNKS) {
            int kbase = (kc + 1) * 8;
            int tap = kbase / CIN;
            int ciA = (kbase % CIN) + lhalf * 4;
            int dy = tap / 3 - 1, dx = tap % 3 - 1;
            int gy = y0 + lpy + dy, gx = x0 + lpx + dx;
            va = make_float4(0.f, 0.f, 0.f, 0.f);
            if (gy >= 0 && gy < H && gx >= 0 && gx < W)
                va = *(const float4*)(inimg + ((size_t)gy * W + gx) * CIN + ciA);
            vb = make_float4(0.f, 0.f, 0.f, 0.f);
            int kg = kbase + bk;
            int cog = cobase + bco;
            if (cog < COUT) {
                const float* wp = w + (size_t)kg * COUT + cog;
                if (cog + 3 < COUT) vb = *(const float4*)wp;
                else {
                    vb.x = wp[0];
                    if (cog + 1 < COUT) vb.y = wp[1];
                    if (cog + 2 < COUT) vb.z = wp[2];
                }
            }
        }
        __syncthreads();

        // compute on buf (FFMA2: pairs over output channels)
        #pragma unroll
        for (int k = 0; k < 8; k++) {
            float a[8];
            *(float4*)&a[0] = *(const float4*)&As[buf][k][row * 8];
            *(float4*)&a[4] = *(const float4*)&As[buf][k][row * 8 + 4];
            u64 b2[4];
            *(ulonglong2*)&b2[0] = *(const ulonglong2*)&Bs[buf][k][col * 8];
            *(ulonglong2*)&b2[2] = *(const ulonglong2*)&Bs[buf][k][col * 8 + 4];
            #pragma unroll
            for (int i = 0; i < 8; i++) {
                u64 ad = dup_f32(a[i]);
                ffma2(acc2[i][0], ad, b2[0]);
                ffma2(acc2[i][1], ad, b2[1]);
                ffma2(acc2[i][2], ad, b2[2]);
                ffma2(acc2[i][3], ad, b2[3]);
            }
        }
        // NOTE: no trailing sync needed — next iteration writes the OTHER
        // buffer, whose last readers were fenced by the sync above.
        __syncthreads();
    }

    // epilogue
    int gy = y0 + row;
    float bv[8];
    #pragma unroll
    for (int j = 0; j < 8; j++) {
        int cog = cobase + col * 8 + j;
        bv[j] = (cog < COUT) ? bias[cog] : 0.f;
    }
    float* outimg = out + (size_t)img * H * W * COUT;
    #pragma unroll
    for (int i = 0; i < 8; i++) {
        int gx = x0 + i;
        const float* accf = (const float*)&acc2[i][0];
        float v[8];
        #pragma unroll
        for (int j = 0; j < 8; j++) {
            float r = accf[j] + bv[j];
            if (RELU) r = fmaxf(r, 0.f);
            v[j] = r;
        }
        int cog = cobase + col * 8;
        float* op = outimg + ((size_t)gy * W + gx) * COUT + cog;
        if (cog + 7 < COUT) {
            *(float4*)op = *(float4*)&v[0];
            *(float4*)(op + 4) = *(float4*)&v[4];
        } else {
            #pragma unroll
            for (int j = 0; j < 8; j++)
                if (cog + j < COUT) op[j] = v[j];
        }
    }
}

// ---------------------------------------------------------------------------
// Fused reg/wt conv with per-batch class selection: 5 output channels only.
// grid (16,16,4), block 256 (16x16 pixel tile)
// ---------------------------------------------------------------------------
__global__ void regsel_kernel(const float* __restrict__ x,
                              const float* __restrict__ reg_w, const float* __restrict__ reg_b,
                              const float* __restrict__ wt_w,  const float* __restrict__ wt_b,
                              const int* __restrict__ cls, float* __restrict__ out) {
    int b = blockIdx.z;
    int c = cls[b];
    __shared__ __align__(16) float ws[9 * 256 * 5];   // 46080 B
    int t = threadIdx.x;
    for (int i = t; i < 9 * 256; i += 256) {
        const float* rp = reg_w + (size_t)i * 12 + 4 * c;
        float* wp = ws + i * 5;
        wp[0] = rp[0]; wp[1] = rp[1]; wp[2] = rp[2]; wp[3] = rp[3];
        wp[4] = wt_w[(size_t)i * 3 + c];
    }
    __syncthreads();
    int px = blockIdx.x * 16 + (t & 15);
    int py = blockIdx.y * 16 + (t >> 4);
    float a0 = reg_b[4 * c], a1 = reg_b[4 * c + 1], a2 = reg_b[4 * c + 2],
          a3 = reg_b[4 * c + 3], a4 = wt_b[c];
    const float* xi = x + (size_t)b * 256 * 256 * 256;
    for (int tap = 0; tap < 9; tap++) {
        int yy = py + tap / 3 - 1, xx = px + tap % 3 - 1;
        if (yy < 0 || yy >= 256 || xx < 0 || xx >= 256) continue;
        const float* ip = xi + ((size_t)yy * 256 + xx) * 256;
        const float* wp = ws + tap * 256 * 5;
        #pragma unroll 2
        for (int ci = 0; ci < 256; ci += 4) {
            float4 v = *(const float4*)(ip + ci);
            float wl[20];
            const float4* w4 = (const float4*)(wp + ci * 5);
            #pragma unroll
            for (int q = 0; q < 5; q++) ((float4*)wl)[q] = w4[q];
            a0 = fmaf(v.x, wl[0], a0);  a1 = fmaf(v.x, wl[1], a1);
            a2 = fmaf(v.x, wl[2], a2);  a3 = fmaf(v.x, wl[3], a3);  a4 = fmaf(v.x, wl[4], a4);
            a0 = fmaf(v.y, wl[5], a0);  a1 = fmaf(v.y, wl[6], a1);
            a2 = fmaf(v.y, wl[7], a2);  a3 = fmaf(v.y, wl[8], a3);  a4 = fmaf(v.y, wl[9], a4);
            a0 = fmaf(v.z, wl[10], a0); a1 = fmaf(v.z, wl[11], a1);
            a2 = fmaf(v.z, wl[12], a2); a3 = fmaf(v.z, wl[13], a3); a4 = fmaf(v.z, wl[14], a4);
            a0 = fmaf(v.w, wl[15], a0); a1 = fmaf(v.w, wl[16], a1);
            a2 = fmaf(v.w, wl[17], a2); a3 = fmaf(v.w, wl[18], a3); a4 = fmaf(v.w, wl[19], a4);
        }
    }
    size_t pix = ((size_t)b * 256 + py) * 256 + px;
    out[OFF_OFFSETS + pix * 2 + 0] = a0;
    out[OFF_OFFSETS + pix * 2 + 1] = a1;
    out[OFF_SIZES   + pix * 2 + 0] = a2;
    out[OFF_SIZES   + pix * 2 + 1] = a3;
    out[OFF_WEIGHTS + pix] = a4;
}

// ---------------------------------------------------------------------------
// Bilinear crop (TF crop_and_resize), 32x32, one block per box.
// ---------------------------------------------------------------------------
__global__ void crop_kernel(const float* __restrict__ feat0,
                            const float* __restrict__ boxes,
                            float* __restrict__ crops) {
    int n = blockIdx.x;            // 0..255 (b*64+p)
    int b = n >> 6;
    const int H = 512, W = 512, C = 64;
    __shared__ int sy0[32], sx0[32];
    __shared__ float swy[32], swx[32];
    const float* bx = boxes + (size_t)n * 4;
    float y1 = bx[0], x1 = bx[1], y2 = bx[2], x2 = bx[3];
    int t = threadIdx.x;
    if (t < 32) {
        float tt = (float)t / 31.0f;
        float ys = y1 * (H - 1) + tt * (y2 - y1) * (H - 1);
        int yy0 = (int)floorf(ys);
        yy0 = min(max(yy0, 0), H - 2);
        sy0[t] = yy0; swy[t] = ys - (float)yy0;
    } else if (t < 64) {
        int i = t - 32;
        float tt = (float)i / 31.0f;
        float xs = x1 * (W - 1) + tt * (x2 - x1) * (W - 1);
        int xx0 = (int)floorf(xs);
        xx0 = min(max(xx0, 0), W - 2);
        sx0[i] = xx0; swx[i] = xs - (float)xx0;
    }
    __syncthreads();
    const float* f = feat0 + (size_t)b * H * W * C;
    float* o = crops + (size_t)n * 32 * 32 * C;
    for (int idx = t; idx < 32 * 32 * C; idx += blockDim.x) {
        int c  = idx & 63;
        int ix = (idx >> 6) & 31;
        int iy = idx >> 11;
        int yy0 = sy0[iy], xx0 = sx0[ix];
        float wy = swy[iy], wx = swx[ix];
        const float* p00 = f + ((size_t)yy0 * W + xx0) * C + c;
        float v00 = p00[0], v01 = p00[C], v10 = p00[(size_t)W * C], v11 = p00[(size_t)W * C + C];
        float top = v00 * (1.f - wx) + v01 * wx;
        float bot = v10 * (1.f - wx) + v11 * wx;
        o[idx] = top * (1.f - wy) + bot * wy;
    }
}

// ---------------------------------------------------------------------------
// so conv with class selection: 1 output channel per crop.
// ---------------------------------------------------------------------------
__global__ void sosel_kernel(const float* __restrict__ s2,
                             const float* __restrict__ so_w, const float* __restrict__ so_b,
                             const int* __restrict__ cls, float* __restrict__ out) {
    int n = blockIdx.x;
    int c = cls[n >> 6];
    __shared__ __align__(16) float ws[9 * 96];
    int t = threadIdx.x;
    for (int i = t; i < 864; i += 256) ws[i] = so_w[(size_t)i * 3 + c];
    __syncthreads();
    float bias = so_b[c];
    const float* sp = s2 + (size_t)n * 32 * 32 * 96;
    for (int pix = t; pix < 1024; pix += 256) {
        int py = pix >> 5, px = pix & 31;
        float acc = bias;
        for (int tap = 0; tap < 9; tap++) {
            int yy = py + tap / 3 - 1, xx = px + tap % 3 - 1;
            if (yy < 0 || yy >= 32 || xx < 0 || xx >= 32) continue;
            const float* ip = sp + ((size_t)yy * 32 + xx) * 96;
            const float* wp = ws + tap * 96;
            #pragma unroll 4
            for (int ci = 0; ci < 96; ci += 4) {
                float4 v = *(const float4*)(ip + ci);
                float4 w = *(const float4*)(wp + ci);
                acc = fmaf(v.x, w.x, acc);
                acc = fmaf(v.y, w.y, acc);
                acc = fmaf(v.z, w.z, acc);
                acc = fmaf(v.w, w.w, acc);
            }
        }
        out[OFF_SEG + (size_t)n * 1024 + pix] = acc;
    }
}

// ---------------------------------------------------------------------------
// Score head: 4x4 avg pool -> dense 6144->256 -> 256->256 -> 256->3 (select)
// One block per crop.
// ---------------------------------------------------------------------------
__global__ void score_kernel(const float* __restrict__ s2,
                             const float* __restrict__ sd1_w, const float* __restrict__ sd1_b,
                             const float* __restrict__ sd2_w, const float* __restrict__ sd2_b,
                             const float* __restrict__ sd3_w, const float* __restrict__ sd3_b,
                             const int* __restrict__ cls, float* __restrict__ out) {
    int n = blockIdx.x;
    int t = threadIdx.x;  // 256
    __shared__ float pooled[6144];
    __shared__ float h1[256], h2[256];
    const float* sp = s2 + (size_t)n * 32 * 32 * 96;
    for (int o = t; o < 6144; o += 256) {
        int c  = o % 96;
        int px = (o / 96) & 7;
        int py = o / 768;
        float s = 0.f;
        #pragma unroll
        for (int i = 0; i < 4; i++)
            #pragma unroll
            for (int j = 0; j < 4; j++)
                s += sp[(((size_t)(py * 4 + i)) * 32 + (px * 4 + j)) * 96 + c];
        pooled[o] = s * (1.f / 16.f);
    }
    __syncthreads();
    float a = sd1_b[t];
    #pragma unroll 4
    for (int k = 0; k < 6144; k++) a = fmaf(pooled[k], sd1_w[(size_t)k * 256 + t], a);
    h1[t] = fmaxf(a, 0.f);
    __syncthreads();
    a = sd2_b[t];
    #pragma unroll 4
    for (int k = 0; k < 256; k++) a = fmaf(h1[k], sd2_w[k * 256 + t], a);
    h2[t] = fmaxf(a, 0.f);
    __syncthreads();
    if (t == 0) {
        int c = cls[n >> 6];
        float acc = sd3_b[c];
        for (int k = 0; k < 256; k++) acc = fmaf(h2[k], sd3_w[k * 3 + c], acc);
        out[OFF_SCORE + n] = acc;
    }
}

// ---------------------------------------------------------------------------
extern "C" void kernel_launch(void* const* d_in, const int* in_sizes, int n_in,
                              void* d_out, int out_size) {
    (void)in_sizes; (void)n_in; (void)out_size;
    const float* feat0 = (const float*)d_in[0];
    const float* feat1 = (const float*)d_in[1];
    const float* feat5 = (const float*)d_in[2];
    const float* boxes = (const float*)d_in[3];
    const float* cb1_w = (const float*)d_in[4];
    const float* cb1_b = (const float*)d_in[5];
    const float* cb2_w = (const float*)d_in[6];
    const float* cb2_b = (const float*)d_in[7];
    const float* reg_w = (const float*)d_in[8];
    const float* reg_b = (const float*)d_in[9];
    const float* wt_w  = (const float*)d_in[10];
    const float* wt_b  = (const float*)d_in[11];
    const float* fc1_w = (const float*)d_in[12];
    const float* fc1_b = (const float*)d_in[13];
    const float* fc2_w = (const float*)d_in[14];
    const float* fc2_b = (const float*)d_in[15];
    const float* fc3_w = (const float*)d_in[16];
    const float* fc3_b = (const float*)d_in[17];
    const float* sc1_w = (const float*)d_in[18];
    const float* sc1_b = (const float*)d_in[19];
    const float* sc2_w = (const float*)d_in[20];
    const float* sc2_b = (const float*)d_in[21];
    const float* so_w  = (const float*)d_in[22];
    const float* so_b  = (const float*)d_in[23];
    const float* sd1_w = (const float*)d_in[24];
    const float* sd1_b = (const float*)d_in[25];
    const float* sd2_w = (const float*)d_in[26];
    const float* sd2_b = (const float*)d_in[27];
    const float* sd3_w = (const float*)d_in[28];
    const float* sd3_b = (const float*)d_in[29];
    float* out = (float*)d_out;

    void *px1, *px2, *pcrops, *ps1, *ps2, *pcls;
    cudaGetSymbolAddress(&px1, g_x1);
    cudaGetSymbolAddress(&px2, g_x2);
    cudaGetSymbolAddress(&pcrops, g_crops);
    cudaGetSymbolAddress(&ps1, g_s1);
    cudaGetSymbolAddress(&ps2, g_s2);
    cudaGetSymbolAddress(&pcls, g_cls);
    float* x1 = (float*)px1;
    float* x2 = (float*)px2;
    float* crops = (float*)pcrops;
    float* s1 = (float*)ps1;
    float* s2 = (float*)ps2;
    int* cls = (int*)pcls;

    // classification first (reg/seg selection depends on cls)
    cls_kernel<<<4, 256>>>(feat5, fc1_w, fc1_b, fc2_w, fc2_b, fc3_w, fc3_b,
                           out + OFF_PREDCLS, cls);

    // crop + segmentation branch
    crop_kernel<<<256, 256>>>(feat0, boxes, crops);
    conv3x3<64, 96, true><<<dim3(4, 2, 256), 256>>>(crops, sc1_w, sc1_b, s1, 32, 32);
    conv3x3<96, 96, true><<<dim3(4, 2, 256), 256>>>(s1, sc2_w, sc2_b, s2, 32, 32);
    sosel_kernel<<<256, 256>>>(s2, so_w, so_b, cls, out);
    score_kernel<<<256, 256>>>(s2, sd1_w, sd1_b, sd2_w, sd2_b, sd3_w, sd3_b, cls, out);

    // regression branch
    conv3x3<128, 256, true><<<dim3(32, 16, 4 * 2), 256>>>(feat1, cb1_w, cb1_b, x1, 256, 256);
    conv3x3<256, 256, true><<<dim3(32, 16, 4 * 2), 256>>>(x1, cb2_w, cb2_b, x2, 256, 256);
    regsel_kernel<<<dim3(16, 16, 4), 256>>>(x2, reg_w, reg_b, wt_w, wt_b, cls, out);
}

// round 4
// speedup vs baseline: 1.9983x; 1.7823x over previous
#include <cuda_runtime.h>
#include <cuda_bf16.h>
#include <math.h>
#include <stdint.h>

typedef unsigned long long u64;

// ---------------------------------------------------------------------------
// Output layout (tuple flattened in order):
// offsets [4,256,256,2], sizes [4,256,256,2], weights [4,256,256,1],
// pred_cls [4,3], seg_sel [256,32,32,1], score_sel [256,1]
// ---------------------------------------------------------------------------
#define OFF_OFFSETS 0
#define OFF_SIZES   524288
#define OFF_WEIGHTS 1048576
#define OFF_PREDCLS 1310720
#define OFF_SEG     1310732
#define OFF_SCORE   1572876

// Scratch (device globals; no allocation allowed)
__device__ float g_x1[4u * 256u * 256u * 256u];      // conv1 out   256MB
__device__ float g_x2[4u * 256u * 256u * 256u];      // conv2 out   256MB
__device__ float g_crops[256u * 32u * 32u * 64u];    // crops        64MB
__device__ float g_s1[256u * 32u * 32u * 96u];       // sc1 out      96MB
__device__ float g_s2[256u * 32u * 32u * 96u];       // sc2 out      96MB
__device__ int   g_cls[4];

// ---------------------------------------------------------------------------
// warp-MMA helpers (arch-generic PTX: sm_80+, compiles for compute_103)
// ---------------------------------------------------------------------------
__device__ __forceinline__ uint32_t smem_u32(const void* p) {
    uint32_t a;
    asm("{ .reg .u64 t; cvta.to.shared.u64 t, %1; cvt.u32.u64 %0, t; }"
        : "=r"(a) : "l"(p));
    return a;
}
__device__ __forceinline__ void ldsm_x4(uint32_t* r, uint32_t a) {
    asm volatile("ldmatrix.sync.aligned.m8n8.x4.shared.b16 {%0,%1,%2,%3}, [%4];"
                 : "=r"(r[0]), "=r"(r[1]), "=r"(r[2]), "=r"(r[3]) : "r"(a));
}
__device__ __forceinline__ void ldsm_x2(uint32_t* r, uint32_t a) {
    asm volatile("ldmatrix.sync.aligned.m8n8.x2.shared.b16 {%0,%1}, [%2];"
                 : "=r"(r[0]), "=r"(r[1]) : "r"(a));
}
__device__ __forceinline__ void mma_bf16(float* d, const uint32_t* a, const uint32_t* b) {
    asm volatile("mma.sync.aligned.m16n8k16.row.col.f32.bf16.bf16.f32 "
                 "{%0,%1,%2,%3}, {%4,%5,%6,%7}, {%8,%9}, {%0,%1,%2,%3};"
                 : "+f"(d[0]), "+f"(d[1]), "+f"(d[2]), "+f"(d[3])
                 : "r"(a[0]), "r"(a[1]), "r"(a[2]), "r"(a[3]),
                   "r"(b[0]), "r"(b[1]));
}

// split 8 fp32 -> 8 bf16 hi (uint4) + 8 bf16 lo (uint4)
__device__ __forceinline__ void split8(const float* v, uint4& hi, uint4& lo) {
    uint32_t h[4], l[4];
    #pragma unroll
    for (int i = 0; i < 4; i++) {
        __nv_bfloat16 h0 = __float2bfloat16_rn(v[2 * i]);
        __nv_bfloat16 h1 = __float2bfloat16_rn(v[2 * i + 1]);
        float r0 = v[2 * i] - __bfloat162float(h0);
        float r1 = v[2 * i + 1] - __bfloat162float(h1);
        __nv_bfloat162 hh; hh.x = h0; hh.y = h1;
        __nv_bfloat162 ll; ll.x = __float2bfloat16_rn(r0); ll.y = __float2bfloat16_rn(r1);
        h[i] = *(uint32_t*)&hh;
        l[i] = *(uint32_t*)&ll;
    }
    hi = make_uint4(h[0], h[1], h[2], h[3]);
    lo = make_uint4(l[0], l[1], l[2], l[3]);
}

// ---------------------------------------------------------------------------
// Tensor-core 3x3 SAME conv (NHWC), implicit GEMM, 2xbf16 split (3 cross terms).
// CTA tile: M=128 pixels (16y x 8x) x N=COUT_TILE couts, K chunks of 32 fp32.
// 8 warps = 4(M: 32 rows each) x 2(N: COUT_TILE/2 each). Double-buffered smem.
// grid: (W/8, H/16, nimg * NT)
// ---------------------------------------------------------------------------
#define CONV_PITCH   40          // bf16 pitch per row (80 B) — conflict-free ldmatrix
#define CONV_ASZ     (128 * 80)  // 10240 B per A component
#define CONV_BSZ     (64 * 80)   // 5120 B per B component
#define CONV_BUFSZ   (2 * CONV_ASZ + 2 * CONV_BSZ)   // 30720
#define CONV_TB      1024
#define CONV_DYN     (CONV_TB + 2 * CONV_BUFSZ)      // 62464

template <int CIN, int COUT_TILE, bool RELU>
__global__ __launch_bounds__(256, 2)
void conv3x3_mma(const float* __restrict__ in, const float* __restrict__ w,
                 const float* __restrict__ bias, float* __restrict__ out,
                 int H, int W, int COUT, int NT) {
    extern __shared__ char sm[];
    const uint32_t sb = smem_u32(sm);
    float* sbias = (float*)sm;

    int t = threadIdx.x, warp = t >> 5, lane = t & 31;
    int img = blockIdx.z / NT, ntile = blockIdx.z % NT;
    int cobase = ntile * COUT_TILE;
    int x0 = blockIdx.x * 8, y0 = blockIdx.y * 16;

    if (t < COUT_TILE) sbias[t] = bias[cobase + t];

    // loader indices
    int lp = t >> 1, lhalf = t & 1;            // A: 2 threads/pixel, 16 floats each
    int lpy = lp >> 3, lpx = lp & 7;
    int brow = t & 63, bkseg = t >> 6;         // B: row=cout, 4 k-segments of 8
    bool bok = brow < COUT_TILE;

    constexpr int NF = COUT_TILE / 16;         // n8-frags per N-warp
    int wm = warp & 3, nw = warp >> 2;
    int nbase = nw * (COUT_TILE / 2);

    float acc[2][NF][4];
    #pragma unroll
    for (int i = 0; i < 2; i++)
        #pragma unroll
        for (int j = 0; j < NF; j++)
            #pragma unroll
            for (int q = 0; q < 4; q++) acc[i][j][q] = 0.f;

    const float* inimg = in + (size_t)img * H * W * CIN;
    const int KCH = CIN * 9 / 32;

    float vA[16];
    float vB[8];

    // ---- prefetch chunk 0 ----
    {
        int gy = y0 + lpy - 1, gx = x0 + lpx - 1;      // tap 0 = (-1,-1)
        bool aok = (gy >= 0 && gy < H && gx >= 0 && gx < W);
        const float* ap = inimg + ((size_t)gy * W + gx) * CIN + lhalf * 16;
        #pragma unroll
        for (int j = 0; j < 4; j++) {
            float4 v = aok ? *(const float4*)(ap + j * 4) : make_float4(0, 0, 0, 0);
            vA[j * 4 + 0] = v.x; vA[j * 4 + 1] = v.y; vA[j * 4 + 2] = v.z; vA[j * 4 + 3] = v.w;
        }
        if (bok) {
            const float* wp = w + (size_t)(bkseg * 8) * COUT + cobase + brow;
            #pragma unroll
            for (int i = 0; i < 8; i++) vB[i] = wp[(size_t)i * COUT];
        }
    }

    for (int kc = 0; kc < KCH; kc++) {
        int buf = kc & 1;
        uint32_t AhiO = CONV_TB + buf * CONV_BUFSZ;
        uint32_t AloO = AhiO + CONV_ASZ;
        uint32_t BhiO = AhiO + 2 * CONV_ASZ;
        uint32_t BloO = BhiO + CONV_BSZ;

        // ---- store prefetched chunk (bf16 hi/lo) ----
        #pragma unroll
        for (int g = 0; g < 2; g++) {
            uint4 hi, lo;
            split8(&vA[g * 8], hi, lo);
            uint32_t aoff = (uint32_t)(lp * 80 + lhalf * 32 + g * 16);
            *(uint4*)(sm + AhiO + aoff) = hi;
            *(uint4*)(sm + AloO + aoff) = lo;
        }
        if (bok) {
            uint4 hi, lo;
            split8(vB, hi, lo);
            uint32_t boff = (uint32_t)(brow * 80 + bkseg * 16);
            *(uint4*)(sm + BhiO + boff) = hi;
            *(uint4*)(sm + BloO + boff) = lo;
        }

        // ---- prefetch next chunk ----
        if (kc + 1 < KCH) {
            int kbase = (kc + 1) * 32;
            int tap = kbase / CIN;
            int dy = tap / 3 - 1, dx = tap % 3 - 1;
            int gy = y0 + lpy + dy, gx = x0 + lpx + dx;
            bool aok = (gy >= 0 && gy < H && gx >= 0 && gx < W);
            const float* ap = inimg + ((size_t)gy * W + gx) * CIN + (kbase % CIN) + lhalf * 16;
            #pragma unroll
            for (int j = 0; j < 4; j++) {
                float4 v = aok ? *(const float4*)(ap + j * 4) : make_float4(0, 0, 0, 0);
                vA[j * 4 + 0] = v.x; vA[j * 4 + 1] = v.y; vA[j * 4 + 2] = v.z; vA[j * 4 + 3] = v.w;
            }
            if (bok) {
                const float* wp = w + (size_t)(kbase + bkseg * 8) * COUT + cobase + brow;
                #pragma unroll
                for (int i = 0; i < 8; i++) vB[i] = wp[(size_t)i * COUT];
            }
        }
        __syncthreads();

        // ---- MMA on buf: 3 cross terms (hi*hi + hi*lo + lo*hi) ----
        #pragma unroll
        for (int k16 = 0; k16 < 2; k16++) {
            uint32_t ah[2][4], al[2][4];
            #pragma unroll
            for (int mi = 0; mi < 2; mi++) {
                uint32_t rowb = (uint32_t)((wm * 32 + mi * 16 + (lane & 15)) * 80
                                           + (k16 * 16 + (lane >> 4) * 8) * 2);
                ldsm_x4(ah[mi], sb + AhiO + rowb);
                ldsm_x4(al[mi], sb + AloO + rowb);
            }
            uint32_t bh[NF][2], bl[NF][2];
            #pragma unroll
            for (int p = 0; p < NF / 2; p++) {
                uint32_t addr = (uint32_t)((nbase + p * 16 + ((lane >> 4) << 3) + (lane & 7)) * 80
                                           + (k16 * 16 + ((lane >> 3) & 1) * 8) * 2);
                uint32_t r4[4];
                ldsm_x4(r4, sb + BhiO + addr);
                bh[2 * p][0] = r4[0]; bh[2 * p][1] = r4[1];
                bh[2 * p + 1][0] = r4[2]; bh[2 * p + 1][1] = r4[3];
                ldsm_x4(r4, sb + BloO + addr);
                bl[2 * p][0] = r4[0]; bl[2 * p][1] = r4[1];
                bl[2 * p + 1][0] = r4[2]; bl[2 * p + 1][1] = r4[3];
            }
            if (NF & 1) {
                int ni = NF - 1;
                uint32_t addr = (uint32_t)((nbase + ni * 8 + (lane & 7)) * 80
                                           + (k16 * 16 + ((lane >> 3) & 1) * 8) * 2);
                ldsm_x2(bh[ni], sb + BhiO + addr);
                ldsm_x2(bl[ni], sb + BloO + addr);
            }
            #pragma unroll
            for (int mi = 0; mi < 2; mi++)
                #pragma unroll
                for (int ni = 0; ni < NF; ni++) {
                    mma_bf16(acc[mi][ni], ah[mi], bh[ni]);
                    mma_bf16(acc[mi][ni], ah[mi], bl[ni]);
                    mma_bf16(acc[mi][ni], al[mi], bh[ni]);
                }
        }
    }

    // ---- epilogue ----
    float* outimg = out + (size_t)img * H * W * COUT;
    #pragma unroll
    for (int mi = 0; mi < 2; mi++) {
        int p0 = wm * 32 + mi * 16 + (lane >> 2);
        #pragma unroll
        for (int half = 0; half < 2; half++) {
            int p = p0 + half * 8;
            int gy = y0 + (p >> 3), gx = x0 + (p & 7);
            float* op = outimg + ((size_t)gy * W + gx) * COUT + cobase;
            #pragma unroll
            for (int ni = 0; ni < NF; ni++) {
                int cl = nbase + ni * 8 + (lane & 3) * 2;
                float r0 = acc[mi][ni][half * 2 + 0] + sbias[cl];
                float r1 = acc[mi][ni][half * 2 + 1] + sbias[cl + 1];
                if (RELU) { r0 = fmaxf(r0, 0.f); r1 = fmaxf(r1, 0.f); }
                float2 v = make_float2(r0, r1);
                *(float2*)(op + cl) = v;
            }
        }
    }
}

// ---------------------------------------------------------------------------
// Classification head: mean -> fc1 -> fc2 -> fc3 -> softmax/argmax
// ---------------------------------------------------------------------------
__global__ void cls_kernel(const float* __restrict__ feat5,
                           const float* __restrict__ fc1_w, const float* __restrict__ fc1_b,
                           const float* __restrict__ fc2_w, const float* __restrict__ fc2_b,
                           const float* __restrict__ fc3_w, const float* __restrict__ fc3_b,
                           float* __restrict__ out_predcls, int* __restrict__ cls) {
    int b = blockIdx.x;
    int t = threadIdx.x;  // 256
    __shared__ float g0[256], g1[256], lg[3];
    const float* f = feat5 + (size_t)b * 16 * 16 * 256;
    float s = 0.f;
    #pragma unroll 4
    for (int p = 0; p < 256; p++) s += f[p * 256 + t];
    g0[t] = s * (1.0f / 256.0f);
    __syncthreads();
    float a = fc1_b[t];
    #pragma unroll 4
    for (int k = 0; k < 256; k++) a = fmaf(g0[k], fc1_w[k * 256 + t], a);
    g1[t] = fmaxf(a, 0.f);
    __syncthreads();
    a = fc2_b[t];
    #pragma unroll 4
    for (int k = 0; k < 256; k++) a = fmaf(g1[k], fc2_w[k * 256 + t], a);
    g0[t] = fmaxf(a, 0.f);
    __syncthreads();
    if (t < 3) {
        a = fc3_b[t];
        for (int k = 0; k < 256; k++) a = fmaf(g0[k], fc3_w[k * 3 + t], a);
        lg[t] = a;
    }
    __syncthreads();
    if (t == 0) {
        float m = fmaxf(lg[0], fmaxf(lg[1], lg[2]));
        float e0 = expf(lg[0] - m), e1 = expf(lg[1] - m), e2 = expf(lg[2] - m);
        float inv = 1.f / (e0 + e1 + e2);
        out_predcls[b * 3 + 0] = e0 * inv;
        out_predcls[b * 3 + 1] = e1 * inv;
        out_predcls[b * 3 + 2] = e2 * inv;
        int c = 0;
        if (lg[1] > lg[0]) c = 1;
        if (lg[2] > lg[c]) c = 2;
        cls[b] = c;
    }
}

// ---------------------------------------------------------------------------
// Fused reg/wt conv with per-batch class selection: 5 output channels only.
// ---------------------------------------------------------------------------
__global__ void regsel_kernel(const float* __restrict__ x,
                              const float* __restrict__ reg_w, const float* __restrict__ reg_b,
                              const float* __restrict__ wt_w,  const float* __restrict__ wt_b,
                              const int* __restrict__ cls, float* __restrict__ out) {
    int b = blockIdx.z;
    int c = cls[b];
    __shared__ __align__(16) float ws[9 * 256 * 5];   // 46080 B
    int t = threadIdx.x;
    for (int i = t; i < 9 * 256; i += 256) {
        const float* rp = reg_w + (size_t)i * 12 + 4 * c;
        float* wp = ws + i * 5;
        wp[0] = rp[0]; wp[1] = rp[1]; wp[2] = rp[2]; wp[3] = rp[3];
        wp[4] = wt_w[(size_t)i * 3 + c];
    }
    __syncthreads();
    int px = blockIdx.x * 16 + (t & 15);
    int py = blockIdx.y * 16 + (t >> 4);
    float a0 = reg_b[4 * c], a1 = reg_b[4 * c + 1], a2 = reg_b[4 * c + 2],
          a3 = reg_b[4 * c + 3], a4 = wt_b[c];
    const float* xi = x + (size_t)b * 256 * 256 * 256;
    for (int tap = 0; tap < 9; tap++) {
        int yy = py + tap / 3 - 1, xx = px + tap % 3 - 1;
        if (yy < 0 || yy >= 256 || xx < 0 || xx >= 256) continue;
        const float* ip = xi + ((size_t)yy * 256 + xx) * 256;
        const float* wp = ws + tap * 256 * 5;
        #pragma unroll 2
        for (int ci = 0; ci < 256; ci += 4) {
            float4 v = *(const float4*)(ip + ci);
            float wl[20];
            const float4* w4 = (const float4*)(wp + ci * 5);
            #pragma unroll
            for (int q = 0; q < 5; q++) ((float4*)wl)[q] = w4[q];
            a0 = fmaf(v.x, wl[0], a0);  a1 = fmaf(v.x, wl[1], a1);
            a2 = fmaf(v.x, wl[2], a2);  a3 = fmaf(v.x, wl[3], a3);  a4 = fmaf(v.x, wl[4], a4);
            a0 = fmaf(v.y, wl[5], a0);  a1 = fmaf(v.y, wl[6], a1);
            a2 = fmaf(v.y, wl[7], a2);  a3 = fmaf(v.y, wl[8], a3);  a4 = fmaf(v.y, wl[9], a4);
            a0 = fmaf(v.z, wl[10], a0); a1 = fmaf(v.z, wl[11], a1);
            a2 = fmaf(v.z, wl[12], a2); a3 = fmaf(v.z, wl[13], a3); a4 = fmaf(v.z, wl[14], a4);
            a0 = fmaf(v.w, wl[15], a0); a1 = fmaf(v.w, wl[16], a1);
            a2 = fmaf(v.w, wl[17], a2); a3 = fmaf(v.w, wl[18], a3); a4 = fmaf(v.w, wl[19], a4);
        }
    }
    size_t pix = ((size_t)b * 256 + py) * 256 + px;
    out[OFF_OFFSETS + pix * 2 + 0] = a0;
    out[OFF_OFFSETS + pix * 2 + 1] = a1;
    out[OFF_SIZES   + pix * 2 + 0] = a2;
    out[OFF_SIZES   + pix * 2 + 1] = a3;
    out[OFF_WEIGHTS + pix] = a4;
}

// ---------------------------------------------------------------------------
// Bilinear crop (TF crop_and_resize), 32x32, one block per box.
// ---------------------------------------------------------------------------
__global__ void crop_kernel(const float* __restrict__ feat0,
                            const float* __restrict__ boxes,
                            float* __restrict__ crops) {
    int n = blockIdx.x;            // 0..255 (b*64+p)
    int b = n >> 6;
    const int H = 512, W = 512, C = 64;
    __shared__ int sy0[32], sx0[32];
    __shared__ float swy[32], swx[32];
    const float* bx = boxes + (size_t)n * 4;
    float y1 = bx[0], x1 = bx[1], y2 = bx[2], x2 = bx[3];
    int t = threadIdx.x;
    if (t < 32) {
        float tt = (float)t / 31.0f;
        float ys = y1 * (H - 1) + tt * (y2 - y1) * (H - 1);
        int yy0 = (int)floorf(ys);
        yy0 = min(max(yy0, 0), H - 2);
        sy0[t] = yy0; swy[t] = ys - (float)yy0;
    } else if (t < 64) {
        int i = t - 32;
        float tt = (float)i / 31.0f;
        float xs = x1 * (W - 1) + tt * (x2 - x1) * (W - 1);
        int xx0 = (int)floorf(xs);
        xx0 = min(max(xx0, 0), W - 2);
        sx0[i] = xx0; swx[i] = xs - (float)xx0;
    }
    __syncthreads();
    const float* f = feat0 + (size_t)b * H * W * C;
    float* o = crops + (size_t)n * 32 * 32 * C;
    for (int idx = t; idx < 32 * 32 * C; idx += blockDim.x) {
        int c  = idx & 63;
        int ix = (idx >> 6) & 31;
        int iy = idx >> 11;
        int yy0 = sy0[iy], xx0 = sx0[ix];
        float wy = swy[iy], wx = swx[ix];
        const float* p00 = f + ((size_t)yy0 * W + xx0) * C + c;
        float v00 = p00[0], v01 = p00[C], v10 = p00[(size_t)W * C], v11 = p00[(size_t)W * C + C];
        float top = v00 * (1.f - wx) + v01 * wx;
        float bot = v10 * (1.f - wx) + v11 * wx;
        o[idx] = top * (1.f - wy) + bot * wy;
    }
}

// ---------------------------------------------------------------------------
// so conv with class selection: 1 output channel per crop.
// ---------------------------------------------------------------------------
__global__ void sosel_kernel(const float* __restrict__ s2,
                             const float* __restrict__ so_w, const float* __restrict__ so_b,
                             const int* __restrict__ cls, float* __restrict__ out) {
    int n = blockIdx.x;
    int c = cls[n >> 6];
    __shared__ __align__(16) float ws[9 * 96];
    int t = threadIdx.x;
    for (int i = t; i < 864; i += 256) ws[i] = so_w[(size_t)i * 3 + c];
    __syncthreads();
    float bias = so_b[c];
    const float* sp = s2 + (size_t)n * 32 * 32 * 96;
    for (int pix = t; pix < 1024; pix += 256) {
        int py = pix >> 5, px = pix & 31;
        float acc = bias;
        for (int tap = 0; tap < 9; tap++) {
            int yy = py + tap / 3 - 1, xx = px + tap % 3 - 1;
            if (yy < 0 || yy >= 32 || xx < 0 || xx >= 32) continue;
            const float* ip = sp + ((size_t)yy * 32 + xx) * 96;
            const float* wp = ws + tap * 96;
            #pragma unroll 4
            for (int ci = 0; ci < 96; ci += 4) {
                float4 v = *(const float4*)(ip + ci);
                float4 w = *(const float4*)(wp + ci);
                acc = fmaf(v.x, w.x, acc);
                acc = fmaf(v.y, w.y, acc);
                acc = fmaf(v.z, w.z, acc);
                acc = fmaf(v.w, w.w, acc);
            }
        }
        out[OFF_SEG + (size_t)n * 1024 + pix] = acc;
    }
}

// ---------------------------------------------------------------------------
// Score head: 4x4 avg pool -> dense 6144->256 -> 256->256 -> 256->3 (select)
// ---------------------------------------------------------------------------
__global__ void score_kernel(const float* __restrict__ s2,
                             const float* __restrict__ sd1_w, const float* __restrict__ sd1_b,
                             const float* __restrict__ sd2_w, const float* __restrict__ sd2_b,
                             const float* __restrict__ sd3_w, const float* __restrict__ sd3_b,
                             const int* __restrict__ cls, float* __restrict__ out) {
    int n = blockIdx.x;
    int t = threadIdx.x;  // 256
    __shared__ float pooled[6144];
    __shared__ float h1[256], h2[256];
    const float* sp = s2 + (size_t)n * 32 * 32 * 96;
    for (int o = t; o < 6144; o += 256) {
        int c  = o % 96;
        int px = (o / 96) & 7;
        int py = o / 768;
        float s = 0.f;
        #pragma unroll
        for (int i = 0; i < 4; i++)
            #pragma unroll
            for (int j = 0; j < 4; j++)
                s += sp[(((size_t)(py * 4 + i)) * 32 + (px * 4 + j)) * 96 + c];
        pooled[o] = s * (1.f / 16.f);
    }
    __syncthreads();
    float a = sd1_b[t];
    #pragma unroll 4
    for (int k = 0; k < 6144; k++) a = fmaf(pooled[k], sd1_w[(size_t)k * 256 + t], a);
    h1[t] = fmaxf(a, 0.f);
    __syncthreads();
    a = sd2_b[t];
    #pragma unroll 4
    for (int k = 0; k < 256; k++) a = fmaf(h1[k], sd2_w[k * 256 + t], a);
    h2[t] = fmaxf(a, 0.f);
    __syncthreads();
    if (t == 0) {
        int c = cls[n >> 6];
        float acc = sd3_b[c];
        for (int k = 0; k < 256; k++) acc = fmaf(h2[k], sd3_w[k * 3 + c], acc);
        out[OFF_SCORE + n] = acc;
    }
}

// ---------------------------------------------------------------------------
extern "C" void kernel_launch(void* const* d_in, const int* in_sizes, int n_in,
                              void* d_out, int out_size) {
    (void)in_sizes; (void)n_in; (void)out_size;
    const float* feat0 = (const float*)d_in[0];
    const float* feat1 = (const float*)d_in[1];
    const float* feat5 = (const float*)d_in[2];
    const float* boxes = (const float*)d_in[3];
    const float* cb1_w = (const float*)d_in[4];
    const float* cb1_b = (const float*)d_in[5];
    const float* cb2_w = (const float*)d_in[6];
    const float* cb2_b = (const float*)d_in[7];
    const float* reg_w = (const float*)d_in[8];
    const float* reg_b = (const float*)d_in[9];
    const float* wt_w  = (const float*)d_in[10];
    const float* wt_b  = (const float*)d_in[11];
    const float* fc1_w = (const float*)d_in[12];
    const float* fc1_b = (const float*)d_in[13];
    const float* fc2_w = (const float*)d_in[14];
    const float* fc2_b = (const float*)d_in[15];
    const float* fc3_w = (const float*)d_in[16];
    const float* fc3_b = (const float*)d_in[17];
    const float* sc1_w = (const float*)d_in[18];
    const float* sc1_b = (const float*)d_in[19];
    const float* sc2_w = (const float*)d_in[20];
    const float* sc2_b = (const float*)d_in[21];
    const float* so_w  = (const float*)d_in[22];
    const float* so_b  = (const float*)d_in[23];
    const float* sd1_w = (const float*)d_in[24];
    const float* sd1_b = (const float*)d_in[25];
    const float* sd2_w = (const float*)d_in[26];
    const float* sd2_b = (const float*)d_in[27];
    const float* sd3_w = (const float*)d_in[28];
    const float* sd3_b = (const float*)d_in[29];
    float* out = (float*)d_out;

    void *px1, *px2, *pcrops, *ps1, *ps2, *pcls;
    cudaGetSymbolAddress(&px1, g_x1);
    cudaGetSymbolAddress(&px2, g_x2);
    cudaGetSymbolAddress(&pcrops, g_crops);
    cudaGetSymbolAddress(&ps1, g_s1);
    cudaGetSymbolAddress(&ps2, g_s2);
    cudaGetSymbolAddress(&pcls, g_cls);
    float* x1 = (float*)px1;
    float* x2 = (float*)px2;
    float* crops = (float*)pcrops;
    float* s1 = (float*)ps1;
    float* s2 = (float*)ps2;
    int* cls = (int*)pcls;

    // opt-in dynamic smem (host-side, idempotent, capture-safe)
    cudaFuncSetAttribute(conv3x3_mma<128, 64, true>,
                         cudaFuncAttributeMaxDynamicSharedMemorySize, CONV_DYN);
    cudaFuncSetAttribute(conv3x3_mma<256, 64, true>,
                         cudaFuncAttributeMaxDynamicSharedMemorySize, CONV_DYN);
    cudaFuncSetAttribute(conv3x3_mma<64, 48, true>,
                         cudaFuncAttributeMaxDynamicSharedMemorySize, CONV_DYN);
    cudaFuncSetAttribute(conv3x3_mma<96, 48, true>,
                         cudaFuncAttributeMaxDynamicSharedMemorySize, CONV_DYN);

    // classification first (reg/seg selection depends on cls)
    cls_kernel<<<4, 256>>>(feat5, fc1_w, fc1_b, fc2_w, fc2_b, fc3_w, fc3_b,
                           out + OFF_PREDCLS, cls);

    // crop + segmentation branch (tensorized convs)
    crop_kernel<<<256, 256>>>(feat0, boxes, crops);
    conv3x3_mma<64, 48, true><<<dim3(4, 2, 512), 256, CONV_DYN>>>(
        crops, sc1_w, sc1_b, s1, 32, 32, 96, 2);
    conv3x3_mma<96, 48, true><<<dim3(4, 2, 512), 256, CONV_DYN>>>(
        s1, sc2_w, sc2_b, s2, 32, 32, 96, 2);
    sosel_kernel<<<256, 256>>>(s2, so_w, so_b, cls, out);
    score_kernel<<<256, 256>>>(s2, sd1_w, sd1_b, sd2_w, sd2_b, sd3_w, sd3_b, cls, out);

    // regression branch (tensorized convs)
    conv3x3_mma<128, 64, true><<<dim3(32, 16, 16), 256, CONV_DYN>>>(
        feat1, cb1_w, cb1_b, x1, 256, 256, 256, 4);
    conv3x3_mma<256, 64, true><<<dim3(32, 16, 16), 256, CONV_DYN>>>(
        x1, cb2_w, cb2_b, x2, 256, 256, 256, 4);
    regsel_kernel<<<dim3(16, 16, 4), 256>>>(x2, reg_w, reg_b, wt_w, wt_b, cls, out);
}